// round 1
// baseline (speedup 1.0000x reference)
#include <cuda_runtime.h>
#include <cstddef>

// x: (256, 3, 256, 256) fp32, z_where: (256, 4) fp32, inverse: int scalar
// out: (256, 3, 64, 64) fp32
static constexpr int B    = 256;
static constexpr int C    = 3;
static constexpr int HIN  = 256;
static constexpr int WIN  = 256;
static constexpr int HOUT = 64;
static constexpr int WOUT = 64;

__global__ __launch_bounds__(256) void st_kernel(
    const float* __restrict__ x,
    const float* __restrict__ zw,
    const int*   __restrict__ inv,
    float* __restrict__ out)
{
    const int b   = blockIdx.x;
    const int tid = threadIdx.x;
    const int oy  = blockIdx.y * 4 + (tid >> 6);
    const int ox  = tid & 63;

    float sx = __ldg(zw + b * 4 + 0);
    float sy = __ldg(zw + b * 4 + 1);
    float tx = __ldg(zw + b * 4 + 2);
    float ty = __ldg(zw + b * 4 + 3);

    if (__ldg(inv)) {
        float isx = 1.0f / (sx + 1e-6f);
        float isy = 1.0f / (sy + 1e-6f);
        tx = -tx * isx;
        ty = -ty * isy;
        sx = isx;
        sy = isy;
    }

    // normalized grid coords
    const float xs = (2.0f * (float)ox + 1.0f) * (1.0f / (float)WOUT) - 1.0f;
    const float ys = (2.0f * (float)oy + 1.0f) * (1.0f / (float)HOUT) - 1.0f;
    const float u = sx * xs + tx;
    const float v = sy * ys + ty;
    const float ix = ((u + 1.0f) * (float)WIN - 1.0f) * 0.5f;
    const float iy = ((v + 1.0f) * (float)HIN - 1.0f) * 0.5f;

    const float fx0 = floorf(ix);
    const float fy0 = floorf(iy);
    const int x0 = (int)fx0, x1 = x0 + 1;
    const int y0 = (int)fy0, y1 = y0 + 1;

    const float wx1 = ix - fx0, wx0 = 1.0f - wx1;
    const float wy1 = iy - fy0, wy0 = 1.0f - wy1;

    const bool vx0 = (x0 >= 0) & (x0 < WIN);
    const bool vx1 = (x1 >= 0) & (x1 < WIN);
    const bool vy0 = (y0 >= 0) & (y0 < HIN);
    const bool vy1 = (y1 >= 0) & (y1 < HIN);

    const int x0c = min(max(x0, 0), WIN - 1);
    const int x1c = min(max(x1, 0), WIN - 1);
    const int y0c = min(max(y0, 0), HIN - 1);
    const int y1c = min(max(y1, 0), HIN - 1);

    const float w00 = (vy0 & vx0) ? wy0 * wx0 : 0.0f;
    const float w01 = (vy0 & vx1) ? wy0 * wx1 : 0.0f;
    const float w10 = (vy1 & vx0) ? wy1 * wx0 : 0.0f;
    const float w11 = (vy1 & vx1) ? wy1 * wx1 : 0.0f;

    const size_t base_in  = (size_t)b * C * HIN * WIN;
    const size_t base_out = (size_t)b * C * HOUT * WOUT + (size_t)oy * WOUT + ox;
    const int o00 = y0c * WIN + x0c;
    const int o01 = y0c * WIN + x1c;
    const int o10 = y1c * WIN + x0c;
    const int o11 = y1c * WIN + x1c;

#pragma unroll
    for (int c = 0; c < C; c++) {
        const float* xc = x + base_in + (size_t)c * HIN * WIN;
        float v00 = __ldg(xc + o00);
        float v01 = __ldg(xc + o01);
        float v10 = __ldg(xc + o10);
        float v11 = __ldg(xc + o11);
        float r = v00 * w00 + v01 * w01 + v10 * w10 + v11 * w11;
        out[base_out + (size_t)c * HOUT * WOUT] = r;
    }
}

extern "C" void kernel_launch(void* const* d_in, const int* in_sizes, int n_in,
                              void* d_out, int out_size)
{
    const float* x   = (const float*)d_in[0];
    const float* zw  = (const float*)d_in[1];
    const int*   inv = (const int*)d_in[2];
    float* out = (float*)d_out;

    dim3 grid(B, HOUT / 4);
    dim3 block(256);
    st_kernel<<<grid, block>>>(x, zw, inv, out);
}

// round 2
// speedup vs baseline: 1.0209x; 1.0209x over previous
#include <cuda_runtime.h>
#include <cstddef>

// x: (256, 3, 256, 256) fp32, z_where: (256, 4) fp32, inverse: int scalar
// out: (256, 3, 64, 64) fp32
static constexpr int B    = 256;
static constexpr int C    = 3;
static constexpr int HIN  = 256;
static constexpr int WIN  = 256;
static constexpr int HOUT = 64;
static constexpr int WOUT = 64;

__global__ __launch_bounds__(256) void st_kernel(
    const float* __restrict__ x,
    const float* __restrict__ zw,
    const int*   __restrict__ inv,
    float* __restrict__ out)
{
    const int b   = blockIdx.x;
    const int tid = threadIdx.x;
    const int row = tid >> 5;          // 0..7
    const int oy  = blockIdx.y * 8 + row;
    const int ox0 = (tid & 31) * 2;    // even, 2 pixels per thread

    float sx = __ldg(zw + b * 4 + 0);
    float sy = __ldg(zw + b * 4 + 1);
    float tx = __ldg(zw + b * 4 + 2);
    float ty = __ldg(zw + b * 4 + 3);

    if (__ldg(inv)) {
        float isx = 1.0f / (sx + 1e-6f);
        float isy = 1.0f / (sy + 1e-6f);
        tx = -tx * isx;
        ty = -ty * isy;
        sx = isx;
        sy = isy;
    }

    // ---- y-side (shared by both pixels) ----
    const float ys = (2.0f * (float)oy + 1.0f) * (1.0f / (float)HOUT) - 1.0f;
    const float v  = sy * ys + ty;
    const float iy = ((v + 1.0f) * (float)HIN - 1.0f) * 0.5f;
    const float fy0 = floorf(iy);
    const int y0 = (int)fy0, y1 = y0 + 1;
    const float wy1 = iy - fy0, wy0 = 1.0f - wy1;
    const bool vy0 = (y0 >= 0) & (y0 < HIN);
    const bool vy1 = (y1 >= 0) & (y1 < HIN);
    const int y0c = min(max(y0, 0), HIN - 1);
    const int y1c = min(max(y1, 0), HIN - 1);
    const int r0 = y0c * WIN;
    const int r1 = y1c * WIN;

    // ---- x-side per pixel ----
    int   xo0[2], xo1[2];
    float w00[2], w01[2], w10[2], w11[2];
#pragma unroll
    for (int p = 0; p < 2; p++) {
        const int ox = ox0 + p;
        const float xs = (2.0f * (float)ox + 1.0f) * (1.0f / (float)WOUT) - 1.0f;
        const float u  = sx * xs + tx;
        const float ix = ((u + 1.0f) * (float)WIN - 1.0f) * 0.5f;
        const float fx0 = floorf(ix);
        const int x0 = (int)fx0, x1 = x0 + 1;
        const float wx1 = ix - fx0, wx0 = 1.0f - wx1;
        const bool vx0 = (x0 >= 0) & (x0 < WIN);
        const bool vx1 = (x1 >= 0) & (x1 < WIN);
        xo0[p] = min(max(x0, 0), WIN - 1);
        xo1[p] = min(max(x1, 0), WIN - 1);
        w00[p] = (vy0 & vx0) ? wy0 * wx0 : 0.0f;
        w01[p] = (vy0 & vx1) ? wy0 * wx1 : 0.0f;
        w10[p] = (vy1 & vx0) ? wy1 * wx0 : 0.0f;
        w11[p] = (vy1 & vx1) ? wy1 * wx1 : 0.0f;
    }

    const size_t base_in  = (size_t)b * C * HIN * WIN;
    const size_t base_out = (size_t)b * C * HOUT * WOUT + (size_t)oy * WOUT + ox0;

#pragma unroll
    for (int c = 0; c < C; c++) {
        const float* xc = x + base_in + (size_t)c * HIN * WIN;
        // issue all 8 loads for this channel before the math (MLP)
        float v00a = __ldg(xc + r0 + xo0[0]);
        float v01a = __ldg(xc + r0 + xo1[0]);
        float v10a = __ldg(xc + r1 + xo0[0]);
        float v11a = __ldg(xc + r1 + xo1[0]);
        float v00b = __ldg(xc + r0 + xo0[1]);
        float v01b = __ldg(xc + r0 + xo1[1]);
        float v10b = __ldg(xc + r1 + xo0[1]);
        float v11b = __ldg(xc + r1 + xo1[1]);

        float2 r;
        r.x = fmaf(v00a, w00[0], fmaf(v01a, w01[0], fmaf(v10a, w10[0], v11a * w11[0])));
        r.y = fmaf(v00b, w00[1], fmaf(v01b, w01[1], fmaf(v10b, w10[1], v11b * w11[1])));
        *reinterpret_cast<float2*>(out + base_out + (size_t)c * HOUT * WOUT) = r;
    }
}

extern "C" void kernel_launch(void* const* d_in, const int* in_sizes, int n_in,
                              void* d_out, int out_size)
{
    const float* x   = (const float*)d_in[0];
    const float* zw  = (const float*)d_in[1];
    const int*   inv = (const int*)d_in[2];
    float* out = (float*)d_out;

    dim3 grid(B, HOUT / 8);
    dim3 block(256);
    st_kernel<<<grid, block>>>(x, zw, inv, out);
}